// round 3
// baseline (speedup 1.0000x reference)
#include <cuda_runtime.h>

#define NB 16384
#define NP 8
#define ND 64
#define NH 128
#define NOPS_ 37
#define OPSTART 16
#define NITER_ 16
#define NCAS 7

#define CAS_GRID 4096
#define DM_GRID 1024

// ---- scratch (static device globals; no allocation) ----
__device__ int g_op[NB];
__device__ int g_carry[NB];
__device__ int g_div[NB];
__device__ int g_mod[NB];
__device__ int g_cnt[4];

__global__ void init_kernel() {
    if (threadIdx.x < 4) g_cnt[threadIdx.x] = 0;
}

// One thread per row: argmax over 37 opcode channels, build compacted row lists.
__global__ void route_kernel(const float* __restrict__ x) {
    int b = blockIdx.x * blockDim.x + threadIdx.x;
    if (b >= NB) return;
    const float* p0 = x + (size_t)b * NP * ND + OPSTART;
    float best = p0[0];
    int op = 0;
    #pragma unroll
    for (int j = 1; j < NOPS_; j++) {
        float v = p0[j];
        if (v > best) { best = v; op = j; }   // strict > keeps first index (jnp.argmax)
    }
    g_op[b] = op;
    bool carry = (op == 0) | (op == 1) | (op == 2) |
                 (op == 10) | (op == 11) | (op == 12) | (op == 13);
    if (carry)        { g_carry[atomicAdd(&g_cnt[0], 1)] = b; }
    else if (op == 3) { g_div  [atomicAdd(&g_cnt[1], 1)] = b; }
    else if (op == 4) { g_mod  [atomicAdd(&g_cnt[2], 1)] = b; }
}

// ---------------------------------------------------------------------------
// Per-row FFN with residual, 128 threads / row, state in shared memory.
// Layer1: thread t owns hidden column t (128 cols), acc[8] over p.
// Layer2: thread t owns (dd = t&63, p-group = 4 rows), acc[4].
// Weight reads are coalesced LDG (L1/L2-resident); x/h reads are LDS.128.
// Ends with __syncthreads(); xs holds the updated row.
// ---------------------------------------------------------------------------
__device__ __forceinline__ void ffn_row(
    float (*xs)[ND], float (*hs)[NH],
    const float* __restrict__ W1, const float* __restrict__ b1,
    const float* __restrict__ W2, const float* __restrict__ b2, int tid)
{
    {
        const int h = tid;                     // 0..127
        const float bias = b1[h];
        float acc[NP];
        #pragma unroll
        for (int p = 0; p < NP; p++) acc[p] = bias;
        #pragma unroll 4
        for (int d4 = 0; d4 < ND; d4 += 4) {
            float w0 = W1[(d4 + 0) * NH + h];
            float w1 = W1[(d4 + 1) * NH + h];
            float w2 = W1[(d4 + 2) * NH + h];
            float w3 = W1[(d4 + 3) * NH + h];
            #pragma unroll
            for (int p = 0; p < NP; p++) {
                float4 xv = *(const float4*)&xs[p][d4];
                acc[p] += xv.x * w0 + xv.y * w1 + xv.z * w2 + xv.w * w3;
            }
        }
        #pragma unroll
        for (int p = 0; p < NP; p++) hs[p][h] = fmaxf(acc[p], 0.0f);
    }
    __syncthreads();
    {
        const int dd = tid & 63;
        const int pg = (tid >> 6) * 4;         // 0 or 4
        float acc[4] = {0.f, 0.f, 0.f, 0.f};
        #pragma unroll 4
        for (int h4 = 0; h4 < NH; h4 += 4) {
            float w0 = W2[(h4 + 0) * ND + dd];
            float w1 = W2[(h4 + 1) * ND + dd];
            float w2 = W2[(h4 + 2) * ND + dd];
            float w3 = W2[(h4 + 3) * ND + dd];
            #pragma unroll
            for (int i = 0; i < 4; i++) {
                float4 hv = *(const float4*)&hs[pg + i][h4];
                acc[i] += hv.x * w0 + hv.y * w1 + hv.z * w2 + hv.w * w3;
            }
        }
        const float bias = b2[dd];
        #pragma unroll
        for (int i = 0; i < 4; i++) xs[pg + i][dd] += acc[i] + bias;
    }
    __syncthreads();
}

// ---------------------------------------------------------------------------
// Per-row carry attention (8 positions), residual, in-place on xs.
// ---------------------------------------------------------------------------
__device__ __forceinline__ void attn_row(
    float (*xs)[ND], float (*qs)[68], float (*ks)[68], float (*vs)[68],
    float (*sc)[8],
    const float* __restrict__ Wq, const float* __restrict__ Wk,
    const float* __restrict__ Wv, int tid)
{
    const int dd = tid & 63;
    const int pg = (tid >> 6) * 4;
    // --- q,k,v projections (thread owns dd column for 4 p-rows) ---
    {
        float aq[4] = {0,0,0,0}, ak[4] = {0,0,0,0}, av[4] = {0,0,0,0};
        #pragma unroll 2
        for (int d4 = 0; d4 < ND; d4 += 4) {
            float xr[4][4];
            #pragma unroll
            for (int i = 0; i < 4; i++) {
                float4 xv = *(const float4*)&xs[pg + i][d4];
                xr[i][0] = xv.x; xr[i][1] = xv.y; xr[i][2] = xv.z; xr[i][3] = xv.w;
            }
            #pragma unroll
            for (int r = 0; r < 4; r++) {
                float wq = Wq[(d4 + r) * ND + dd];
                float wk = Wk[(d4 + r) * ND + dd];
                float wv = Wv[(d4 + r) * ND + dd];
                #pragma unroll
                for (int i = 0; i < 4; i++) {
                    aq[i] += xr[i][r] * wq;
                    ak[i] += xr[i][r] * wk;
                    av[i] += xr[i][r] * wv;
                }
            }
        }
        #pragma unroll
        for (int i = 0; i < 4; i++) {
            qs[pg + i][dd] = aq[i];
            ks[pg + i][dd] = ak[i];
            vs[pg + i][dd] = av[i];
        }
    }
    __syncthreads();
    // --- scores: 64 (p,q') dot products of length 64, scale 1/sqrt(64) ---
    if (tid < 64) {
        int p = tid >> 3, qq = tid & 7;
        float s = 0.f;
        #pragma unroll
        for (int d = 0; d < ND; d += 4) {
            float4 qv = *(const float4*)&qs[p][d];
            float4 kv = *(const float4*)&ks[qq][d];
            s += qv.x * kv.x + qv.y * kv.y + qv.z * kv.z + qv.w * kv.w;
        }
        sc[p][qq] = s * 0.125f;
    }
    __syncthreads();
    // --- softmax over q' (8 elems per p-row) ---
    if (tid < 8) {
        float m = sc[tid][0];
        #pragma unroll
        for (int q = 1; q < 8; q++) m = fmaxf(m, sc[tid][q]);
        float e[8], sum = 0.f;
        #pragma unroll
        for (int q = 0; q < 8; q++) { e[q] = __expf(sc[tid][q] - m); sum += e[q]; }
        float inv = 1.0f / sum;
        #pragma unroll
        for (int q = 0; q < 8; q++) sc[tid][q] = e[q] * inv;
    }
    __syncthreads();
    // --- out: xs += s @ v ---
    {
        float ao[4] = {0,0,0,0};
        #pragma unroll
        for (int q = 0; q < 8; q++) {
            float vq = vs[q][dd];
            #pragma unroll
            for (int i = 0; i < 4; i++) ao[i] += sc[pg + i][q] * vq;
        }
        #pragma unroll
        for (int i = 0; i < 4; i++) xs[pg + i][dd] += ao[i];
    }
    __syncthreads();
}

// ---------------------------------------------------------------------------
// Full-batch opcode-routed MoE (stage 1 and final stage). One block per row.
// ---------------------------------------------------------------------------
__global__ void moe_all_kernel(
    const float* __restrict__ xin, float* __restrict__ xout,
    const float* __restrict__ W1, const float* __restrict__ b1,
    const float* __restrict__ W2, const float* __restrict__ b2)
{
    __shared__ __align__(16) float xs[NP][ND];
    __shared__ __align__(16) float hs[NP][NH];
    const int b = blockIdx.x;
    const int tid = threadIdx.x;
    const int op = g_op[b];
    ((float4*)&xs[0][0])[tid] = ((const float4*)(xin + (size_t)b * NP * ND))[tid];
    __syncthreads();
    ffn_row(xs, hs,
            W1 + (size_t)op * ND * NH, b1 + op * NH,
            W2 + (size_t)op * NH * ND, b2 + op * ND, tid);
    ((float4*)(xout + (size_t)b * NP * ND))[tid] = ((const float4*)&xs[0][0])[tid];
}

// ---------------------------------------------------------------------------
// Fused 7-iteration carry cascade: only carry rows, row lives in SMEM.
// ---------------------------------------------------------------------------
__global__ void cascade_kernel(
    float* __restrict__ xbuf,
    const float* __restrict__ Wq, const float* __restrict__ Wk,
    const float* __restrict__ Wv,
    const float* __restrict__ Wc1, const float* __restrict__ bc1,
    const float* __restrict__ Wc2, const float* __restrict__ bc2)
{
    __shared__ __align__(16) float xs[NP][ND];
    __shared__ __align__(16) float hs[NP][NH];
    __shared__ __align__(16) float qs[NP][68];
    __shared__ __align__(16) float ks[NP][68];
    __shared__ __align__(16) float vs[NP][68];
    __shared__ float sc[NP][8];
    const int tid = threadIdx.x;
    const int n = g_cnt[0];
    for (int idx = blockIdx.x; idx < n; idx += CAS_GRID) {
        const int b = g_carry[idx];
        const int op = g_op[b];
        float* xrow = xbuf + (size_t)b * NP * ND;
        ((float4*)&xs[0][0])[tid] = ((const float4*)xrow)[tid];
        const float* W1 = Wc1 + (size_t)op * ND * NH;
        const float* B1 = bc1 + op * NH;
        const float* W2 = Wc2 + (size_t)op * NH * ND;
        const float* B2 = bc2 + op * ND;
        __syncthreads();
        #pragma unroll 1
        for (int it = 0; it < NCAS; it++) {
            attn_row(xs, qs, ks, vs, sc, Wq, Wk, Wv, tid);
            ffn_row(xs, hs, W1, B1, W2, B2, tid);
        }
        ((float4*)xrow)[tid] = ((const float4*)&xs[0][0])[tid];
        __syncthreads();
    }
}

// ---------------------------------------------------------------------------
// Fused 16-iteration DIV and MOD chains (disjoint row sets, one launch).
// Blocks [0, DM_GRID) walk the div list; [DM_GRID, 2*DM_GRID) the mod list.
// ---------------------------------------------------------------------------
__global__ void divmod_kernel(
    float* __restrict__ xbuf,
    const float* __restrict__ Wd1, const float* __restrict__ bd1,
    const float* __restrict__ Wd2, const float* __restrict__ bd2,
    const float* __restrict__ Wm1, const float* __restrict__ bm1,
    const float* __restrict__ Wm2, const float* __restrict__ bm2)
{
    __shared__ __align__(16) float xs[NP][ND];
    __shared__ __align__(16) float hs[NP][NH];
    const int tid = threadIdx.x;
    const bool is_mod = blockIdx.x >= DM_GRID;
    const int j0 = is_mod ? (blockIdx.x - DM_GRID) : blockIdx.x;
    const int n = is_mod ? g_cnt[2] : g_cnt[1];
    const int* list = is_mod ? g_mod : g_div;
    const float* W1b = is_mod ? Wm1 : Wd1;
    const float* b1b = is_mod ? bm1 : bd1;
    const float* W2b = is_mod ? Wm2 : Wd2;
    const float* b2b = is_mod ? bm2 : bd2;
    for (int idx = j0; idx < n; idx += DM_GRID) {
        const int b = list[idx];
        float* xrow = xbuf + (size_t)b * NP * ND;
        ((float4*)&xs[0][0])[tid] = ((const float4*)xrow)[tid];
        __syncthreads();
        #pragma unroll 1
        for (int i = 0; i < NITER_; i++)
            ffn_row(xs, hs,
                    W1b + (size_t)i * ND * NH, b1b + i * NH,
                    W2b + (size_t)i * NH * ND, b2b + i * ND, tid);
        ((float4*)xrow)[tid] = ((const float4*)&xs[0][0])[tid];
        __syncthreads();
    }
}

// ---------------------------------------------------------------------------
// Launch sequence (graph-capturable: kernels only, scratch is static).
// Input order per metadata: x, Wi1,bi1,Wi2,bi2, Wq,Wk,Wv, Wc1,bc1,Wc2,bc2,
//                           Wd1,bd1,Wd2,bd2, Wm1,bm1,Wm2,bm2, Wf1,bf1,Wf2,bf2
// ---------------------------------------------------------------------------
extern "C" void kernel_launch(void* const* d_in, const int* in_sizes, int n_in,
                              void* d_out, int out_size)
{
    const float* x   = (const float*)d_in[0];
    const float* Wi1 = (const float*)d_in[1];
    const float* bi1 = (const float*)d_in[2];
    const float* Wi2 = (const float*)d_in[3];
    const float* bi2 = (const float*)d_in[4];
    const float* Wq  = (const float*)d_in[5];
    const float* Wk  = (const float*)d_in[6];
    const float* Wv  = (const float*)d_in[7];
    const float* Wc1 = (const float*)d_in[8];
    const float* bc1 = (const float*)d_in[9];
    const float* Wc2 = (const float*)d_in[10];
    const float* bc2 = (const float*)d_in[11];
    const float* Wd1 = (const float*)d_in[12];
    const float* bd1 = (const float*)d_in[13];
    const float* Wd2 = (const float*)d_in[14];
    const float* bd2 = (const float*)d_in[15];
    const float* Wm1 = (const float*)d_in[16];
    const float* bm1 = (const float*)d_in[17];
    const float* Wm2 = (const float*)d_in[18];
    const float* bm2 = (const float*)d_in[19];
    const float* Wf1 = (const float*)d_in[20];
    const float* bf1 = (const float*)d_in[21];
    const float* Wf2 = (const float*)d_in[22];
    const float* bf2 = (const float*)d_in[23];
    float* out = (float*)d_out;

    init_kernel<<<1, 32>>>();
    route_kernel<<<(NB + 127) / 128, 128>>>(x);
    // Stage 1: initial experts, reads input, writes full output buffer.
    moe_all_kernel<<<NB, 128>>>(x, out, Wi1, bi1, Wi2, bi2);
    // Stages 2-3: fused 7x (attn + carry experts), carry rows only, in place.
    cascade_kernel<<<CAS_GRID, 128>>>(out, Wq, Wk, Wv, Wc1, bc1, Wc2, bc2);
    // 16x DIV FFNs + 16x MOD FFNs, masked rows only, fused, in place.
    divmod_kernel<<<2 * DM_GRID, 128>>>(out, Wd1, bd1, Wd2, bd2,
                                        Wm1, bm1, Wm2, bm2);
    // Stage 4: finalization experts, in place.
    moe_all_kernel<<<NB, 128>>>(out, out, Wf1, bf1, Wf2, bf2);
}

// round 4
// speedup vs baseline: 1.2617x; 1.2617x over previous
#include <cuda_runtime.h>

#define NB 16384
#define NP 8
#define ND 64
#define NH 128
#define NOPS_ 37
#define OPSTART 16
#define NITER_ 16
#define NCAS 7

#define CAS_BLK 2048
#define DIV_BLK 384
#define MOD_BLK 384

// ---- scratch (static device globals; no allocation) ----
__device__ int g_op[NB];
__device__ int g_carry[NB];
__device__ int g_div[NB];
__device__ int g_mod[NB];
__device__ int g_cnt[4];

__global__ void init_kernel() {
    if (threadIdx.x < 4) g_cnt[threadIdx.x] = 0;
}

// One thread per row: argmax over 37 opcode channels, build compacted lists.
__global__ void route_kernel(const float* __restrict__ x) {
    int b = blockIdx.x * blockDim.x + threadIdx.x;
    if (b >= NB) return;
    const float* p0 = x + (size_t)b * NP * ND + OPSTART;
    float best = p0[0];
    int op = 0;
    #pragma unroll
    for (int j = 1; j < NOPS_; j++) {
        float v = p0[j];
        if (v > best) { best = v; op = j; }   // strict > keeps first (jnp.argmax)
    }
    g_op[b] = op;
    bool carry = (op == 0) | (op == 1) | (op == 2) |
                 (op == 10) | (op == 11) | (op == 12) | (op == 13);
    if (carry)        { g_carry[atomicAdd(&g_cnt[0], 1)] = b; }
    else if (op == 3) { g_div  [atomicAdd(&g_cnt[1], 1)] = b; }
    else if (op == 4) { g_mod  [atomicAdd(&g_cnt[2], 1)] = b; }
}

// ---------------------------------------------------------------------------
// Group FFN: 64 threads per row. 2-D register tiles to maximize FFMA density.
// Layer1: thread owns (4 p, 4 h). Layer2: thread owns (4 p, 2 dd).
// Ends with __syncthreads(); xs holds updated row state.
// ---------------------------------------------------------------------------
__device__ __forceinline__ void ffn_g(
    float (*xs)[ND], float (*hs)[NH],
    const float* __restrict__ W1, const float* __restrict__ b1,
    const float* __restrict__ W2, const float* __restrict__ b2, int t)
{
    // ---- layer 1: h = relu(x @ W1 + b1) ----
    {
        const int p0 = (t >> 5) * 4;
        const int h0 = (t & 31) * 4;
        float4 bb = __ldg((const float4*)(b1 + h0));
        float acc[4][4];
        #pragma unroll
        for (int i = 0; i < 4; i++) {
            acc[i][0] = bb.x; acc[i][1] = bb.y; acc[i][2] = bb.z; acc[i][3] = bb.w;
        }
        #pragma unroll 2
        for (int d4 = 0; d4 < ND; d4 += 4) {
            float xv[4][4];
            #pragma unroll
            for (int i = 0; i < 4; i++) {
                float4 v = *(const float4*)&xs[p0 + i][d4];
                xv[i][0] = v.x; xv[i][1] = v.y; xv[i][2] = v.z; xv[i][3] = v.w;
            }
            #pragma unroll
            for (int r = 0; r < 4; r++) {
                float4 w = __ldg((const float4*)(W1 + (d4 + r) * NH + h0));
                #pragma unroll
                for (int i = 0; i < 4; i++) {
                    acc[i][0] = fmaf(xv[i][r], w.x, acc[i][0]);
                    acc[i][1] = fmaf(xv[i][r], w.y, acc[i][1]);
                    acc[i][2] = fmaf(xv[i][r], w.z, acc[i][2]);
                    acc[i][3] = fmaf(xv[i][r], w.w, acc[i][3]);
                }
            }
        }
        #pragma unroll
        for (int i = 0; i < 4; i++) {
            float4 o;
            o.x = fmaxf(acc[i][0], 0.f); o.y = fmaxf(acc[i][1], 0.f);
            o.z = fmaxf(acc[i][2], 0.f); o.w = fmaxf(acc[i][3], 0.f);
            *(float4*)&hs[p0 + i][h0] = o;
        }
    }
    __syncthreads();
    // ---- layer 2: x += h @ W2 + b2 ----
    {
        const int p0  = (t >> 5) * 4;
        const int dd0 = (t & 31) * 2;
        float2 bb = __ldg((const float2*)(b2 + dd0));
        float acc[4][2];
        #pragma unroll
        for (int i = 0; i < 4; i++) { acc[i][0] = 0.f; acc[i][1] = 0.f; }
        #pragma unroll 4
        for (int h4 = 0; h4 < NH; h4 += 4) {
            float hv[4][4];
            #pragma unroll
            for (int i = 0; i < 4; i++) {
                float4 v = *(const float4*)&hs[p0 + i][h4];
                hv[i][0] = v.x; hv[i][1] = v.y; hv[i][2] = v.z; hv[i][3] = v.w;
            }
            #pragma unroll
            for (int r = 0; r < 4; r++) {
                float2 w = __ldg((const float2*)(W2 + (h4 + r) * ND + dd0));
                #pragma unroll
                for (int i = 0; i < 4; i++) {
                    acc[i][0] = fmaf(hv[i][r], w.x, acc[i][0]);
                    acc[i][1] = fmaf(hv[i][r], w.y, acc[i][1]);
                }
            }
        }
        #pragma unroll
        for (int i = 0; i < 4; i++) {
            float2 cur = *(const float2*)&xs[p0 + i][dd0];
            cur.x += acc[i][0] + bb.x;
            cur.y += acc[i][1] + bb.y;
            *(float2*)&xs[p0 + i][dd0] = cur;
        }
    }
    __syncthreads();
}

// ---------------------------------------------------------------------------
// Group attention: 64 threads per row. qkv tiled (4 p, 2 c), 3 mats fused.
// ---------------------------------------------------------------------------
__device__ __forceinline__ void attn_g(
    float (*xs)[ND], float (*qs)[ND], float (*ks)[ND], float (*vs)[ND],
    float (*sc)[8],
    const float* __restrict__ Wq, const float* __restrict__ Wk,
    const float* __restrict__ Wv, int t)
{
    const int p0 = (t >> 5) * 4;
    const int c0 = (t & 31) * 2;
    // ---- q,k,v projections ----
    {
        float aq[4][2], ak[4][2], av[4][2];
        #pragma unroll
        for (int i = 0; i < 4; i++) {
            aq[i][0] = aq[i][1] = 0.f;
            ak[i][0] = ak[i][1] = 0.f;
            av[i][0] = av[i][1] = 0.f;
        }
        #pragma unroll 2
        for (int d4 = 0; d4 < ND; d4 += 4) {
            float xv[4][4];
            #pragma unroll
            for (int i = 0; i < 4; i++) {
                float4 v = *(const float4*)&xs[p0 + i][d4];
                xv[i][0] = v.x; xv[i][1] = v.y; xv[i][2] = v.z; xv[i][3] = v.w;
            }
            #pragma unroll
            for (int r = 0; r < 4; r++) {
                float2 wq = __ldg((const float2*)(Wq + (d4 + r) * ND + c0));
                float2 wk = __ldg((const float2*)(Wk + (d4 + r) * ND + c0));
                float2 wv = __ldg((const float2*)(Wv + (d4 + r) * ND + c0));
                #pragma unroll
                for (int i = 0; i < 4; i++) {
                    float xr = xv[i][r];
                    aq[i][0] = fmaf(xr, wq.x, aq[i][0]);
                    aq[i][1] = fmaf(xr, wq.y, aq[i][1]);
                    ak[i][0] = fmaf(xr, wk.x, ak[i][0]);
                    ak[i][1] = fmaf(xr, wk.y, ak[i][1]);
                    av[i][0] = fmaf(xr, wv.x, av[i][0]);
                    av[i][1] = fmaf(xr, wv.y, av[i][1]);
                }
            }
        }
        #pragma unroll
        for (int i = 0; i < 4; i++) {
            *(float2*)&qs[p0 + i][c0] = make_float2(aq[i][0], aq[i][1]);
            *(float2*)&ks[p0 + i][c0] = make_float2(ak[i][0], ak[i][1]);
            *(float2*)&vs[p0 + i][c0] = make_float2(av[i][0], av[i][1]);
        }
    }
    __syncthreads();
    // ---- scores: 64 (p, q') dot products of length 64 ----
    {
        int p = t >> 3, qq = t & 7;
        float s = 0.f;
        #pragma unroll
        for (int d4 = 0; d4 < ND; d4 += 4) {
            float4 qv = *(const float4*)&qs[p][d4];
            float4 kv = *(const float4*)&ks[qq][d4];
            s = fmaf(qv.x, kv.x, s); s = fmaf(qv.y, kv.y, s);
            s = fmaf(qv.z, kv.z, s); s = fmaf(qv.w, kv.w, s);
        }
        sc[p][qq] = s * 0.125f;
    }
    __syncthreads();
    // ---- softmax over q' ----
    if (t < 8) {
        float m = sc[t][0];
        #pragma unroll
        for (int q = 1; q < 8; q++) m = fmaxf(m, sc[t][q]);
        float e[8], sum = 0.f;
        #pragma unroll
        for (int q = 0; q < 8; q++) { e[q] = __expf(sc[t][q] - m); sum += e[q]; }
        float inv = 1.0f / sum;
        #pragma unroll
        for (int q = 0; q < 8; q++) sc[t][q] = e[q] * inv;
    }
    __syncthreads();
    // ---- out: xs += s @ v ----
    {
        float ao[4][2];
        #pragma unroll
        for (int i = 0; i < 4; i++) { ao[i][0] = 0.f; ao[i][1] = 0.f; }
        #pragma unroll
        for (int q = 0; q < 8; q++) {
            float2 vq = *(const float2*)&vs[q][c0];
            #pragma unroll
            for (int i = 0; i < 4; i++) {
                float s = sc[p0 + i][q];
                ao[i][0] = fmaf(s, vq.x, ao[i][0]);
                ao[i][1] = fmaf(s, vq.y, ao[i][1]);
            }
        }
        #pragma unroll
        for (int i = 0; i < 4; i++) {
            float2 cur = *(const float2*)&xs[p0 + i][c0];
            cur.x += ao[i][0]; cur.y += ao[i][1];
            *(float2*)&xs[p0 + i][c0] = cur;
        }
    }
    __syncthreads();
}

// ---------------------------------------------------------------------------
// Full-batch opcode-routed MoE. 2 rows per 128-thread block.
// ---------------------------------------------------------------------------
__global__ void __launch_bounds__(128) moe_all_kernel(
    const float* __restrict__ xin, float* __restrict__ xout,
    const float* __restrict__ W1, const float* __restrict__ b1,
    const float* __restrict__ W2, const float* __restrict__ b2)
{
    __shared__ __align__(16) float xs[2][NP][ND];
    __shared__ __align__(16) float hs[2][NP][NH];
    const int tid = threadIdx.x;
    const int g = tid >> 6, t = tid & 63;
    const int b = blockIdx.x * 2 + g;
    const int op = g_op[b];
    const float4* src = (const float4*)(xin + (size_t)b * NP * ND);
    float4* mine = (float4*)&xs[g][0][0];
    mine[t] = src[t];
    mine[t + 64] = src[t + 64];
    __syncthreads();
    ffn_g(xs[g], hs[g],
          W1 + (size_t)op * ND * NH, b1 + op * NH,
          W2 + (size_t)op * NH * ND, b2 + op * ND, t);
    float4* dst = (float4*)(xout + (size_t)b * NP * ND);
    dst[t] = mine[t];
    dst[t + 64] = mine[t + 64];
}

// ---------------------------------------------------------------------------
// Fused sparse phase: cascade (7x attn+FFN), DIV chain, MOD chain in ONE
// launch over disjoint block ranges — fills the machine concurrently.
// 2 rows per block; both groups iterate in lockstep (masked when out of rows).
// ---------------------------------------------------------------------------
__global__ void __launch_bounds__(128) sparse_kernel(
    float* __restrict__ xbuf,
    const float* __restrict__ Wq, const float* __restrict__ Wk,
    const float* __restrict__ Wv,
    const float* __restrict__ Wc1, const float* __restrict__ bc1,
    const float* __restrict__ Wc2, const float* __restrict__ bc2,
    const float* __restrict__ Wd1, const float* __restrict__ bd1,
    const float* __restrict__ Wd2, const float* __restrict__ bd2,
    const float* __restrict__ Wm1, const float* __restrict__ bm1,
    const float* __restrict__ Wm2, const float* __restrict__ bm2)
{
    __shared__ __align__(16) float xs[2][NP][ND];
    __shared__ __align__(16) float hs[2][NP][NH];
    __shared__ __align__(16) float qs[2][NP][ND];
    __shared__ __align__(16) float ks[2][NP][ND];
    __shared__ __align__(16) float vs[2][NP][ND];
    __shared__ float sc[2][NP][8];
    const int tid = threadIdx.x;
    const int g = tid >> 6, t = tid & 63;
    float4* mine = (float4*)&xs[g][0][0];

    if (blockIdx.x < CAS_BLK) {
        // ---------------- carry cascade ----------------
        const int n = g_cnt[0];
        for (int base = blockIdx.x * 2; base < n; base += CAS_BLK * 2) {
            const int idx = base + g;
            const bool valid = idx < n;
            const int b = g_carry[valid ? idx : base];
            const int op = g_op[b];
            float* xrow = xbuf + (size_t)b * NP * ND;
            if (valid) {
                mine[t] = ((const float4*)xrow)[t];
                mine[t + 64] = ((const float4*)xrow)[t + 64];
            }
            const float* W1 = Wc1 + (size_t)op * ND * NH;
            const float* B1 = bc1 + op * NH;
            const float* W2 = Wc2 + (size_t)op * NH * ND;
            const float* B2 = bc2 + op * ND;
            __syncthreads();
            #pragma unroll 1
            for (int it = 0; it < NCAS; it++) {
                attn_g(xs[g], qs[g], ks[g], vs[g], sc[g], Wq, Wk, Wv, t);
                ffn_g(xs[g], hs[g], W1, B1, W2, B2, t);
            }
            if (valid) {
                ((float4*)xrow)[t] = mine[t];
                ((float4*)xrow)[t + 64] = mine[t + 64];
            }
            __syncthreads();
        }
    } else {
        // ---------------- DIV / MOD iterative chains ----------------
        const bool is_mod = blockIdx.x >= CAS_BLK + DIV_BLK;
        const int bid = blockIdx.x - (is_mod ? CAS_BLK + DIV_BLK : CAS_BLK);
        const int nblk = is_mod ? MOD_BLK : DIV_BLK;
        const int n = is_mod ? g_cnt[2] : g_cnt[1];
        const int* list = is_mod ? g_mod : g_div;
        const float* W1b = is_mod ? Wm1 : Wd1;
        const float* b1b = is_mod ? bm1 : bd1;
        const float* W2b = is_mod ? Wm2 : Wd2;
        const float* b2b = is_mod ? bm2 : bd2;
        for (int base = bid * 2; base < n; base += nblk * 2) {
            const int idx = base + g;
            const bool valid = idx < n;
            const int b = list[valid ? idx : base];
            float* xrow = xbuf + (size_t)b * NP * ND;
            if (valid) {
                mine[t] = ((const float4*)xrow)[t];
                mine[t + 64] = ((const float4*)xrow)[t + 64];
            }
            __syncthreads();
            #pragma unroll 1
            for (int i = 0; i < NITER_; i++)
                ffn_g(xs[g], hs[g],
                      W1b + (size_t)i * ND * NH, b1b + i * NH,
                      W2b + (size_t)i * NH * ND, b2b + i * ND, t);
            if (valid) {
                ((float4*)xrow)[t] = mine[t];
                ((float4*)xrow)[t + 64] = mine[t + 64];
            }
            __syncthreads();
        }
    }
}

// ---------------------------------------------------------------------------
// Launch sequence (graph-capturable; scratch is static device globals).
// ---------------------------------------------------------------------------
extern "C" void kernel_launch(void* const* d_in, const int* in_sizes, int n_in,
                              void* d_out, int out_size)
{
    const float* x   = (const float*)d_in[0];
    const float* Wi1 = (const float*)d_in[1];
    const float* bi1 = (const float*)d_in[2];
    const float* Wi2 = (const float*)d_in[3];
    const float* bi2 = (const float*)d_in[4];
    const float* Wq  = (const float*)d_in[5];
    const float* Wk  = (const float*)d_in[6];
    const float* Wv  = (const float*)d_in[7];
    const float* Wc1 = (const float*)d_in[8];
    const float* bc1 = (const float*)d_in[9];
    const float* Wc2 = (const float*)d_in[10];
    const float* bc2 = (const float*)d_in[11];
    const float* Wd1 = (const float*)d_in[12];
    const float* bd1 = (const float*)d_in[13];
    const float* Wd2 = (const float*)d_in[14];
    const float* bd2 = (const float*)d_in[15];
    const float* Wm1 = (const float*)d_in[16];
    const float* bm1 = (const float*)d_in[17];
    const float* Wm2 = (const float*)d_in[18];
    const float* bm2 = (const float*)d_in[19];
    const float* Wf1 = (const float*)d_in[20];
    const float* bf1 = (const float*)d_in[21];
    const float* Wf2 = (const float*)d_in[22];
    const float* bf2 = (const float*)d_in[23];
    float* out = (float*)d_out;

    init_kernel<<<1, 32>>>();
    route_kernel<<<(NB + 127) / 128, 128>>>(x);
    // Stage 1: initial experts (all rows), x -> out.
    moe_all_kernel<<<NB / 2, 128>>>(x, out, Wi1, bi1, Wi2, bi2);
    // Sparse phase: carry cascade + div + mod chains, one concurrent launch.
    sparse_kernel<<<CAS_BLK + DIV_BLK + MOD_BLK, 128>>>(
        out, Wq, Wk, Wv, Wc1, bc1, Wc2, bc2,
        Wd1, bd1, Wd2, bd2, Wm1, bm1, Wm2, bm2);
    // Stage 4: finalization experts (all rows), in place.
    moe_all_kernel<<<NB / 2, 128>>>(out, out, Wf1, bf1, Wf2, bf2);
}

// round 5
// speedup vs baseline: 1.7365x; 1.3762x over previous
#include <cuda_runtime.h>

#define NB 16384
#define NP 8
#define ND 64
#define NH 128
#define NOPS_ 37
#define OPSTART 16
#define NITER_ 16
#define NCAS 7

#define SP_BLOCKS 760          // ~5 blocks/SM; work stealing absorbs the rest
#define WS_STRIDE 1632         // per-row workspace floats: max(8*132, 3*8*68)
#define HS_STRIDE 132          // padded hidden row
#define QK_STRIDE 68           // padded qkv row (bank-conflict avoidance)

typedef unsigned long long ull;

// ---- scratch (static device globals; no allocation) ----
__device__ int g_op[NB];
__device__ int g_carry[NB];
__device__ int g_div[NB];
__device__ int g_mod[NB];
__device__ int g_cnt[4];
__device__ int g_claim[4];

__global__ void init_kernel() {
    if (threadIdx.x < 4) { g_cnt[threadIdx.x] = 0; g_claim[threadIdx.x] = 0; }
}

// One thread per row: argmax over 37 opcode channels, build compacted lists.
__global__ void route_kernel(const float* __restrict__ x) {
    int b = blockIdx.x * blockDim.x + threadIdx.x;
    if (b >= NB) return;
    const float* p0 = x + (size_t)b * NP * ND + OPSTART;
    float best = p0[0];
    int op = 0;
    #pragma unroll
    for (int j = 1; j < NOPS_; j++) {
        float v = p0[j];
        if (v > best) { best = v; op = j; }   // strict > keeps first (jnp.argmax)
    }
    g_op[b] = op;
    bool carry = (op == 0) | (op == 1) | (op == 2) |
                 (op == 10) | (op == 11) | (op == 12) | (op == 13);
    if (carry)        { g_carry[atomicAdd(&g_cnt[0], 1)] = b; }
    else if (op == 3) { g_div  [atomicAdd(&g_cnt[1], 1)] = b; }
    else if (op == 4) { g_mod  [atomicAdd(&g_cnt[2], 1)] = b; }
}

// ---- packed fp32x2 primitives (FFMA2 path; bit-identical fp32 numerics) ----
__device__ __forceinline__ ull pack2(float x, float y) {
    ull r;
    asm("mov.b64 %0, {%1, %2};"
        : "=l"(r) : "r"(__float_as_uint(x)), "r"(__float_as_uint(y)));
    return r;
}
__device__ __forceinline__ ull fma2(ull a, ull b, ull c) {
    ull d;
    asm("fma.rn.f32x2 %0, %1, %2, %3;" : "=l"(d) : "l"(a), "l"(b), "l"(c));
    return d;
}
__device__ __forceinline__ float2 unpack2(ull v) {
    unsigned int lo, hi;
    asm("mov.b64 {%0, %1}, %2;" : "=r"(lo), "=r"(hi) : "l"(v));
    return make_float2(__uint_as_float(lo), __uint_as_float(hi));
}

// ---------------------------------------------------------------------------
// Warp-level FFN with residual; one warp owns one row. State xs[8][64] and
// workspace ws (hidden at stride 132) in this warp's SMEM slice.
// Packed-pair accumulators; weights load pre-packed via ulonglong2.
// ---------------------------------------------------------------------------
__device__ __forceinline__ void ffn_w(
    float (*xs)[ND], float* ws,
    const float* __restrict__ W1, const float* __restrict__ b1,
    const float* __restrict__ W2, const float* __restrict__ b2, int lane)
{
    // ---- layer 1: h = relu(x @ W1 + b1); lane owns h columns [4*lane, +4) ----
    {
        const int h0 = lane * 4;
        float4 bb = __ldg((const float4*)(b1 + h0));
        ull acc[NP][2];
        {
            ull b01 = pack2(bb.x, bb.y), b23 = pack2(bb.z, bb.w);
            #pragma unroll
            for (int p = 0; p < NP; p++) { acc[p][0] = b01; acc[p][1] = b23; }
        }
        #pragma unroll 2
        for (int d4 = 0; d4 < ND; d4 += 4) {
            ulonglong2 w0 = __ldg((const ulonglong2*)(W1 + (d4 + 0) * NH + h0));
            ulonglong2 w1 = __ldg((const ulonglong2*)(W1 + (d4 + 1) * NH + h0));
            ulonglong2 w2 = __ldg((const ulonglong2*)(W1 + (d4 + 2) * NH + h0));
            ulonglong2 w3 = __ldg((const ulonglong2*)(W1 + (d4 + 3) * NH + h0));
            #pragma unroll
            for (int p = 0; p < NP; p++) {
                float4 xv = *(const float4*)&xs[p][d4];
                ull xx;
                xx = pack2(xv.x, xv.x);
                acc[p][0] = fma2(xx, w0.x, acc[p][0]);
                acc[p][1] = fma2(xx, w0.y, acc[p][1]);
                xx = pack2(xv.y, xv.y);
                acc[p][0] = fma2(xx, w1.x, acc[p][0]);
                acc[p][1] = fma2(xx, w1.y, acc[p][1]);
                xx = pack2(xv.z, xv.z);
                acc[p][0] = fma2(xx, w2.x, acc[p][0]);
                acc[p][1] = fma2(xx, w2.y, acc[p][1]);
                xx = pack2(xv.w, xv.w);
                acc[p][0] = fma2(xx, w3.x, acc[p][0]);
                acc[p][1] = fma2(xx, w3.y, acc[p][1]);
            }
        }
        #pragma unroll
        for (int p = 0; p < NP; p++) {
            float2 a = unpack2(acc[p][0]), b = unpack2(acc[p][1]);
            float4 o;
            o.x = fmaxf(a.x, 0.f); o.y = fmaxf(a.y, 0.f);
            o.z = fmaxf(b.x, 0.f); o.w = fmaxf(b.y, 0.f);
            *(float4*)&ws[p * HS_STRIDE + h0] = o;
        }
    }
    __syncwarp();
    // ---- layer 2: x += h @ W2 + b2; lane owns 4 dd cols, half the p rows ----
    {
        const int dd0 = (lane & 15) * 4;
        const int ph  = (lane >> 4) * 4;
        ull acc[4][2];
        #pragma unroll
        for (int i = 0; i < 4; i++) { acc[i][0] = 0ull; acc[i][1] = 0ull; }
        #pragma unroll 2
        for (int h4 = 0; h4 < NH; h4 += 4) {
            ulonglong2 w0 = __ldg((const ulonglong2*)(W2 + (h4 + 0) * ND + dd0));
            ulonglong2 w1 = __ldg((const ulonglong2*)(W2 + (h4 + 1) * ND + dd0));
            ulonglong2 w2 = __ldg((const ulonglong2*)(W2 + (h4 + 2) * ND + dd0));
            ulonglong2 w3 = __ldg((const ulonglong2*)(W2 + (h4 + 3) * ND + dd0));
            #pragma unroll
            for (int i = 0; i < 4; i++) {
                float4 hv = *(const float4*)&ws[(ph + i) * HS_STRIDE + h4];
                ull xx;
                xx = pack2(hv.x, hv.x);
                acc[i][0] = fma2(xx, w0.x, acc[i][0]);
                acc[i][1] = fma2(xx, w0.y, acc[i][1]);
                xx = pack2(hv.y, hv.y);
                acc[i][0] = fma2(xx, w1.x, acc[i][0]);
                acc[i][1] = fma2(xx, w1.y, acc[i][1]);
                xx = pack2(hv.z, hv.z);
                acc[i][0] = fma2(xx, w2.x, acc[i][0]);
                acc[i][1] = fma2(xx, w2.y, acc[i][1]);
                xx = pack2(hv.w, hv.w);
                acc[i][0] = fma2(xx, w3.x, acc[i][0]);
                acc[i][1] = fma2(xx, w3.y, acc[i][1]);
            }
        }
        float4 bb = __ldg((const float4*)(b2 + dd0));
        #pragma unroll
        for (int i = 0; i < 4; i++) {
            float2 a = unpack2(acc[i][0]), b = unpack2(acc[i][1]);
            float4 cur = *(const float4*)&xs[ph + i][dd0];
            cur.x += a.x + bb.x; cur.y += a.y + bb.y;
            cur.z += b.x + bb.z; cur.w += b.y + bb.w;
            *(float4*)&xs[ph + i][dd0] = cur;
        }
    }
    __syncwarp();
}

// ---------------------------------------------------------------------------
// Warp-level carry attention, residual, in-place. Workspace layout in ws:
// qs @ 0, ks @ 544, vs @ 1088, each 8 rows of stride 68.
// ---------------------------------------------------------------------------
__device__ __forceinline__ void attn_w(
    float (*xs)[ND], float* ws, float (*sc)[8],
    const float* __restrict__ Wq, const float* __restrict__ Wk,
    const float* __restrict__ Wv, int lane)
{
    const int c0 = lane * 2;
    float* qsm = ws;
    float* ksm = ws + 544;
    float* vsm = ws + 1088;
    // ---- q,k,v projections: lane owns column pair c0; 3 mats share x pack ----
    {
        ull aq[NP], ak[NP], av[NP];
        #pragma unroll
        for (int p = 0; p < NP; p++) { aq[p] = 0ull; ak[p] = 0ull; av[p] = 0ull; }
        #pragma unroll 2
        for (int d4 = 0; d4 < ND; d4 += 4) {
            ull wq0 = __ldg((const ull*)(Wq + (d4 + 0) * ND + c0));
            ull wq1 = __ldg((const ull*)(Wq + (d4 + 1) * ND + c0));
            ull wq2 = __ldg((const ull*)(Wq + (d4 + 2) * ND + c0));
            ull wq3 = __ldg((const ull*)(Wq + (d4 + 3) * ND + c0));
            ull wk0 = __ldg((const ull*)(Wk + (d4 + 0) * ND + c0));
            ull wk1 = __ldg((const ull*)(Wk + (d4 + 1) * ND + c0));
            ull wk2 = __ldg((const ull*)(Wk + (d4 + 2) * ND + c0));
            ull wk3 = __ldg((const ull*)(Wk + (d4 + 3) * ND + c0));
            ull wv0 = __ldg((const ull*)(Wv + (d4 + 0) * ND + c0));
            ull wv1 = __ldg((const ull*)(Wv + (d4 + 1) * ND + c0));
            ull wv2 = __ldg((const ull*)(Wv + (d4 + 2) * ND + c0));
            ull wv3 = __ldg((const ull*)(Wv + (d4 + 3) * ND + c0));
            #pragma unroll
            for (int p = 0; p < NP; p++) {
                float4 xv = *(const float4*)&xs[p][d4];
                ull xx;
                xx = pack2(xv.x, xv.x);
                aq[p] = fma2(xx, wq0, aq[p]);
                ak[p] = fma2(xx, wk0, ak[p]);
                av[p] = fma2(xx, wv0, av[p]);
                xx = pack2(xv.y, xv.y);
                aq[p] = fma2(xx, wq1, aq[p]);
                ak[p] = fma2(xx, wk1, ak[p]);
                av[p] = fma2(xx, wv1, av[p]);
                xx = pack2(xv.z, xv.z);
                aq[p] = fma2(xx, wq2, aq[p]);
                ak[p] = fma2(xx, wk2, ak[p]);
                av[p] = fma2(xx, wv2, av[p]);
                xx = pack2(xv.w, xv.w);
                aq[p] = fma2(xx, wq3, aq[p]);
                ak[p] = fma2(xx, wk3, ak[p]);
                av[p] = fma2(xx, wv3, av[p]);
            }
        }
        #pragma unroll
        for (int p = 0; p < NP; p++) {
            float2 q = unpack2(aq[p]);
            float2 k = unpack2(ak[p]);
            float2 v = unpack2(av[p]);
            *(float2*)&qsm[p * QK_STRIDE + c0] = q;
            *(float2*)&ksm[p * QK_STRIDE + c0] = k;
            *(float2*)&vsm[p * QK_STRIDE + c0] = v;
        }
    }
    __syncwarp();
    // ---- scores: each lane does 2 of the 64 (p,q') dots ----
    #pragma unroll
    for (int j = 0; j < 2; j++) {
        int idx = lane + 32 * j;
        int p = idx >> 3, qq = idx & 7;
        float s = 0.f;
        #pragma unroll
        for (int d4 = 0; d4 < ND; d4 += 4) {
            float4 qv = *(const float4*)&qsm[p * QK_STRIDE + d4];
            float4 kv = *(const float4*)&ksm[qq * QK_STRIDE + d4];
            s = fmaf(qv.x, kv.x, s); s = fmaf(qv.y, kv.y, s);
            s = fmaf(qv.z, kv.z, s); s = fmaf(qv.w, kv.w, s);
        }
        sc[p][qq] = s * 0.125f;
    }
    __syncwarp();
    // ---- softmax over q' (lanes 0-7, one row each) ----
    if (lane < 8) {
        float m = sc[lane][0];
        #pragma unroll
        for (int q = 1; q < 8; q++) m = fmaxf(m, sc[lane][q]);
        float e[8], sum = 0.f;
        #pragma unroll
        for (int q = 0; q < 8; q++) { e[q] = __expf(sc[lane][q] - m); sum += e[q]; }
        float inv = 1.0f / sum;
        #pragma unroll
        for (int q = 0; q < 8; q++) sc[lane][q] = e[q] * inv;
    }
    __syncwarp();
    // ---- out: xs += s @ v (lane owns column pair c0) ----
    {
        ull vq[8];
        #pragma unroll
        for (int q = 0; q < 8; q++)
            vq[q] = *(const ull*)&vsm[q * QK_STRIDE + c0];
        #pragma unroll
        for (int p = 0; p < NP; p++) {
            float4 s0 = *(const float4*)&sc[p][0];
            float4 s1 = *(const float4*)&sc[p][4];
            ull a = 0ull;
            a = fma2(pack2(s0.x, s0.x), vq[0], a);
            a = fma2(pack2(s0.y, s0.y), vq[1], a);
            a = fma2(pack2(s0.z, s0.z), vq[2], a);
            a = fma2(pack2(s0.w, s0.w), vq[3], a);
            a = fma2(pack2(s1.x, s1.x), vq[4], a);
            a = fma2(pack2(s1.y, s1.y), vq[5], a);
            a = fma2(pack2(s1.z, s1.z), vq[6], a);
            a = fma2(pack2(s1.w, s1.w), vq[7], a);
            float2 r = unpack2(a);
            float2 cur = *(const float2*)&xs[p][c0];
            cur.x += r.x; cur.y += r.y;
            *(float2*)&xs[p][c0] = cur;
        }
    }
    __syncwarp();
}

// ---------------------------------------------------------------------------
// Full-batch opcode-routed MoE: one warp per row, 4 rows per block, no BARs.
// ---------------------------------------------------------------------------
__global__ void __launch_bounds__(128) moe_all_kernel(
    const float* __restrict__ xin, float* __restrict__ xout,
    const float* __restrict__ W1, const float* __restrict__ b1,
    const float* __restrict__ W2, const float* __restrict__ b2)
{
    __shared__ __align__(16) float xs[4][NP][ND];
    __shared__ __align__(16) float ws[4][NP * HS_STRIDE];
    const int w = threadIdx.x >> 5, lane = threadIdx.x & 31;
    const int b = blockIdx.x * 4 + w;
    const int op = g_op[b];
    const float4* src = (const float4*)(xin + (size_t)b * NP * ND);
    float4* mine = (float4*)&xs[w][0][0];
    #pragma unroll
    for (int j = 0; j < 4; j++) mine[lane + 32 * j] = src[lane + 32 * j];
    __syncwarp();
    ffn_w(xs[w], ws[w],
          W1 + (size_t)op * ND * NH, b1 + op * NH,
          W2 + (size_t)op * NH * ND, b2 + op * ND, lane);
    float4* dst = (float4*)(xout + (size_t)b * NP * ND);
    #pragma unroll
    for (int j = 0; j < 4; j++) dst[lane + 32 * j] = mine[lane + 32 * j];
}

// ---------------------------------------------------------------------------
// Fused sparse phase: warps steal rows from three pools (cascade, div, mod)
// via atomic claim counters. One warp per row, zero block barriers.
// ---------------------------------------------------------------------------
__global__ void __launch_bounds__(128) sparse_kernel(
    float* __restrict__ xbuf,
    const float* __restrict__ Wq, const float* __restrict__ Wk,
    const float* __restrict__ Wv,
    const float* __restrict__ Wc1, const float* __restrict__ bc1,
    const float* __restrict__ Wc2, const float* __restrict__ bc2,
    const float* __restrict__ Wd1, const float* __restrict__ bd1,
    const float* __restrict__ Wd2, const float* __restrict__ bd2,
    const float* __restrict__ Wm1, const float* __restrict__ bm1,
    const float* __restrict__ Wm2, const float* __restrict__ bm2)
{
    __shared__ __align__(16) float xs[4][NP][ND];
    __shared__ __align__(16) float ws[4][WS_STRIDE];
    __shared__ __align__(16) float sc[4][NP][8];
    const int w = threadIdx.x >> 5, lane = threadIdx.x & 31;
    float (*xsr)[ND] = xs[w];
    float* wsr = ws[w];
    float4* mine = (float4*)&xsr[0][0];

    // ---------------- pool 0: carry cascade ----------------
    const int n0 = g_cnt[0];
    for (;;) {
        int idx = 0;
        if (lane == 0) idx = atomicAdd(&g_claim[0], 1);
        idx = __shfl_sync(0xffffffffu, idx, 0);
        if (idx >= n0) break;
        const int b = g_carry[idx];
        const int op = g_op[b];
        float* xrow = xbuf + (size_t)b * NP * ND;
        #pragma unroll
        for (int j = 0; j < 4; j++) mine[lane + 32 * j] = ((const float4*)xrow)[lane + 32 * j];
        const float* W1 = Wc1 + (size_t)op * ND * NH;
        const float* B1 = bc1 + op * NH;
        const float* W2 = Wc2 + (size_t)op * NH * ND;
        const float* B2 = bc2 + op * ND;
        __syncwarp();
        #pragma unroll 1
        for (int it = 0; it < NCAS; it++) {
            attn_w(xsr, wsr, sc[w], Wq, Wk, Wv, lane);
            ffn_w(xsr, wsr, W1, B1, W2, B2, lane);
        }
        #pragma unroll
        for (int j = 0; j < 4; j++) ((float4*)xrow)[lane + 32 * j] = mine[lane + 32 * j];
        __syncwarp();
    }
    // ---------------- pool 1: DIV chain ----------------
    const int n1 = g_cnt[1];
    for (;;) {
        int idx = 0;
        if (lane == 0) idx = atomicAdd(&g_claim[1], 1);
        idx = __shfl_sync(0xffffffffu, idx, 0);
        if (idx >= n1) break;
        const int b = g_div[idx];
        float* xrow = xbuf + (size_t)b * NP * ND;
        #pragma unroll
        for (int j = 0; j < 4; j++) mine[lane + 32 * j] = ((const float4*)xrow)[lane + 32 * j];
        __syncwarp();
        #pragma unroll 1
        for (int i = 0; i < NITER_; i++)
            ffn_w(xsr, wsr,
                  Wd1 + (size_t)i * ND * NH, bd1 + i * NH,
                  Wd2 + (size_t)i * NH * ND, bd2 + i * ND, lane);
        #pragma unroll
        for (int j = 0; j < 4; j++) ((float4*)xrow)[lane + 32 * j] = mine[lane + 32 * j];
        __syncwarp();
    }
    // ---------------- pool 2: MOD chain ----------------
    const int n2 = g_cnt[2];
    for (;;) {
        int idx = 0;
        if (lane == 0) idx = atomicAdd(&g_claim[2], 1);
        idx = __shfl_sync(0xffffffffu, idx, 0);
        if (idx >= n2) break;
        const int b = g_mod[idx];
        float* xrow = xbuf + (size_t)b * NP * ND;
        #pragma unroll
        for (int j = 0; j < 4; j++) mine[lane + 32 * j] = ((const float4*)xrow)[lane + 32 * j];
        __syncwarp();
        #pragma unroll 1
        for (int i = 0; i < NITER_; i++)
            ffn_w(xsr, wsr,
                  Wm1 + (size_t)i * ND * NH, bm1 + i * NH,
                  Wm2 + (size_t)i * NH * ND, bm2 + i * ND, lane);
        #pragma unroll
        for (int j = 0; j < 4; j++) ((float4*)xrow)[lane + 32 * j] = mine[lane + 32 * j];
        __syncwarp();
    }
}

// ---------------------------------------------------------------------------
// Launch sequence (graph-capturable; scratch is static device globals).
// ---------------------------------------------------------------------------
extern "C" void kernel_launch(void* const* d_in, const int* in_sizes, int n_in,
                              void* d_out, int out_size)
{
    const float* x   = (const float*)d_in[0];
    const float* Wi1 = (const float*)d_in[1];
    const float* bi1 = (const float*)d_in[2];
    const float* Wi2 = (const float*)d_in[3];
    const float* bi2 = (const float*)d_in[4];
    const float* Wq  = (const float*)d_in[5];
    const float* Wk  = (const float*)d_in[6];
    const float* Wv  = (const float*)d_in[7];
    const float* Wc1 = (const float*)d_in[8];
    const float* bc1 = (const float*)d_in[9];
    const float* Wc2 = (const float*)d_in[10];
    const float* bc2 = (const float*)d_in[11];
    const float* Wd1 = (const float*)d_in[12];
    const float* bd1 = (const float*)d_in[13];
    const float* Wd2 = (const float*)d_in[14];
    const float* bd2 = (const float*)d_in[15];
    const float* Wm1 = (const float*)d_in[16];
    const float* bm1 = (const float*)d_in[17];
    const float* Wm2 = (const float*)d_in[18];
    const float* bm2 = (const float*)d_in[19];
    const float* Wf1 = (const float*)d_in[20];
    const float* bf1 = (const float*)d_in[21];
    const float* Wf2 = (const float*)d_in[22];
    const float* bf2 = (const float*)d_in[23];
    float* out = (float*)d_out;

    init_kernel<<<1, 32>>>();
    route_kernel<<<(NB + 127) / 128, 128>>>(x);
    // Stage 1: initial experts (all rows), x -> out.
    moe_all_kernel<<<NB / 4, 128>>>(x, out, Wi1, bi1, Wi2, bi2);
    // Sparse phase: work-stealing warps over cascade/div/mod row pools.
    sparse_kernel<<<SP_BLOCKS, 128>>>(
        out, Wq, Wk, Wv, Wc1, bc1, Wc2, bc2,
        Wd1, bd1, Wd2, bd2, Wm1, bm1, Wm2, bm2);
    // Stage 4: finalization experts (all rows), in place.
    moe_all_kernel<<<NB / 4, 128>>>(out, out, Wf1, bf1, Wf2, bf2);
}